// round 11
// baseline (speedup 1.0000x reference)
#include <cuda_runtime.h>
#include <cuda_bf16.h>
#include <cuda_fp16.h>
#include <math.h>
#include <stdint.h>

#define EMB 768
#define HEADS 12
#define HD 64
#define SEQ 4096
#define QKV_LD (3 * EMB)   // 2304
#define LOG2E 1.4426950408889634f

// Scratch (static device globals — no allocation)
__device__ __align__(16) float g_qkv[(size_t)SEQ * QKV_LD];  // [l][3*emb] : Q|K|V
__device__ __align__(16) float g_ctx[(size_t)SEQ * EMB];     // [l][h*64 + c]
// Interleaved fp16 limb planes: per (h,row) a 128-half row of 32 groups
// {hi(2k),hi(2k+1),lo(2k),lo(2k+1)}.
__device__ __align__(16) __half g_k16[(size_t)HEADS * SEQ * 128];  // [h][k][grp]
__device__ __align__(16) __half g_v16[(size_t)HEADS * HD * SEQ * 2]; // [h][c][kgrp]

// ---------------------------------------------------------------------------
// HMMA helpers (mma.sync — supported on base sm_103 target)
// ---------------------------------------------------------------------------
__device__ __forceinline__ void mma_bf16(float* d, const uint32_t* a, const uint32_t* b) {
    asm volatile(
        "mma.sync.aligned.m16n8k16.row.col.f32.bf16.bf16.f32 "
        "{%0,%1,%2,%3}, {%4,%5,%6,%7}, {%8,%9}, {%0,%1,%2,%3};"
        : "+f"(d[0]), "+f"(d[1]), "+f"(d[2]), "+f"(d[3])
        : "r"(a[0]), "r"(a[1]), "r"(a[2]), "r"(a[3]), "r"(b[0]), "r"(b[1]));
}
__device__ __forceinline__ void mma_f16(float* d, const uint32_t* a, const uint32_t* b) {
    asm volatile(
        "mma.sync.aligned.m16n8k16.row.col.f32.f16.f16.f32 "
        "{%0,%1,%2,%3}, {%4,%5,%6,%7}, {%8,%9}, {%0,%1,%2,%3};"
        : "+f"(d[0]), "+f"(d[1]), "+f"(d[2]), "+f"(d[3])
        : "r"(a[0]), "r"(a[1]), "r"(a[2]), "r"(a[3]), "r"(b[0]), "r"(b[1]));
}
__device__ __forceinline__ uint32_t h2bits(__half2 h) { return *(uint32_t*)&h; }
__device__ __forceinline__ float ex2f(float x) {
    float r; asm("ex2.approx.ftz.f32 %0, %1;" : "=f"(r) : "f"(x)); return r;
}

// fp32 pair -> fp16 hi/lo limbs (packed f16x2: x -> low half)
__device__ __forceinline__ void split_h2(float x, float y, uint32_t& hi, uint32_t& lo) {
    __half2 h = __floats2half2_rn(x, y);
    float2 f = __half22float2(h);
    __half2 l = __floats2half2_rn(x - f.x, y - f.y);
    hi = h2bits(h);
    lo = h2bits(l);
}

// fp32 pair -> bf16 limb split (for projection GEMMs)
__device__ __forceinline__ void split_pair_bf(
    float x, float y, uint32_t& h, uint32_t& m, uint32_t& l, bool want3)
{
    __nv_bfloat162 hb = __float22bfloat162_rn(make_float2(x, y));
    float2 hf = __bfloat1622float2(hb);
    float rx = x - hf.x, ry = y - hf.y;
    __nv_bfloat162 mb = __float22bfloat162_rn(make_float2(rx, ry));
    h = *(uint32_t*)&hb;
    m = *(uint32_t*)&mb;
    if (want3) {
        float2 mf = __bfloat1622float2(mb);
        __nv_bfloat162 lb = __float22bfloat162_rn(make_float2(rx - mf.x, ry - mf.y));
        l = *(uint32_t*)&lb;
    } else {
        l = 0;
    }
}

// ---------------------------------------------------------------------------
// HMMA GEMM: C[M,N] = A[M,K] @ B[N,K]^T (+bias), fp32 via bf16 limb split.
// (unchanged — passing; 2 CTAs/SM, tensor 62%)
// ---------------------------------------------------------------------------
#define LT (128 * 40)   // bf16 elements per limb tile

template<int NSPLIT>
__global__ __launch_bounds__(256, 2) void hmma_gemm_abt(
    const float* __restrict__ A, const float* __restrict__ B,
    const float* __restrict__ bias, float* __restrict__ C,
    int M, int N, int K)
{
    extern __shared__ __align__(16) char smem[];
    __nv_bfloat16* As = (__nv_bfloat16*)smem;
    __nv_bfloat16* Bs = As + NSPLIT * LT;

    const int tid  = threadIdx.x;
    const int lane = tid & 31;
    const int wid  = tid >> 5;
    const int wm   = wid >> 2;
    const int wn   = wid & 3;
    const int grp  = lane >> 2;
    const int tg   = lane & 3;
    const int bm0  = blockIdx.y * 128;
    const int bn0  = blockIdx.x * 128;

    float d[4][4][4];
#pragma unroll
    for (int am = 0; am < 4; am++)
#pragma unroll
        for (int an = 0; an < 4; an++)
#pragma unroll
            for (int r = 0; r < 4; r++) d[am][an][r] = 0.0f;

    const int NPR = (NSPLIT == 3) ? 6 : 3;
    const int PA[6] = {0, 0, 1, 0, 2, 1};
    const int PB[6] = {0, 1, 0, 2, 0, 1};

    for (int k0 = 0; k0 < K; k0 += 32) {
        __syncthreads();
#pragma unroll
        for (int half = 0; half < 2; half++) {
            const float* src = half ? (B + (size_t)bn0 * K) : (A + (size_t)bm0 * K);
            __nv_bfloat16* dst = half ? Bs : As;
#pragma unroll
            for (int it = 0; it < 2; it++) {
                const int f   = tid + it * 256;
                const int row = f >> 2;
                const int c8  = f & 3;
                const float* p = src + (size_t)row * K + k0 + c8 * 8;
                float4 v0 = *(const float4*)p;
                float4 v1 = *(const float4*)(p + 4);
                uint32_t h[4], m[4], l[4];
                split_pair_bf(v0.x, v0.y, h[0], m[0], l[0], NSPLIT == 3);
                split_pair_bf(v0.z, v0.w, h[1], m[1], l[1], NSPLIT == 3);
                split_pair_bf(v1.x, v1.y, h[2], m[2], l[2], NSPLIT == 3);
                split_pair_bf(v1.z, v1.w, h[3], m[3], l[3], NSPLIT == 3);
                const int base = row * 40 + c8 * 8;
#pragma unroll
                for (int j = 0; j < 4; j++) {
                    *(uint32_t*)&dst[0 * LT + base + j * 2] = h[j];
                    *(uint32_t*)&dst[1 * LT + base + j * 2] = m[j];
                    if (NSPLIT == 3)
                        *(uint32_t*)&dst[2 * LT + base + j * 2] = l[j];
                }
            }
        }
        __syncthreads();

#pragma unroll
        for (int ks = 0; ks < 2; ks++) {
#pragma unroll
            for (int p = 0; p < NPR; p++) {
                const int la = PA[p], lb = PB[p];
                uint32_t afr[4][4];
#pragma unroll
                for (int am = 0; am < 4; am++) {
                    const __nv_bfloat16* ap =
                        As + la * LT + (wm * 64 + am * 16 + grp) * 40 + ks * 16 + tg * 2;
                    afr[am][0] = *(const uint32_t*)ap;
                    afr[am][1] = *(const uint32_t*)(ap + 8 * 40);
                    afr[am][2] = *(const uint32_t*)(ap + 8);
                    afr[am][3] = *(const uint32_t*)(ap + 8 * 40 + 8);
                }
#pragma unroll
                for (int an = 0; an < 4; an++) {
                    const __nv_bfloat16* bp =
                        Bs + lb * LT + (wn * 32 + an * 8 + grp) * 40 + ks * 16 + tg * 2;
                    uint32_t bfr[2];
                    bfr[0] = *(const uint32_t*)bp;
                    bfr[1] = *(const uint32_t*)(bp + 8);
#pragma unroll
                    for (int am = 0; am < 4; am++)
                        mma_bf16(d[am][an], afr[am], bfr);
                }
            }
        }
    }

#pragma unroll
    for (int am = 0; am < 4; am++) {
        const int r0 = bm0 + wm * 64 + am * 16 + grp;
#pragma unroll
        for (int an = 0; an < 4; an++) {
            const int c0 = bn0 + wn * 32 + an * 8 + tg * 2;
            float bv0 = 0.0f, bv1 = 0.0f;
            if (bias) { bv0 = bias[c0]; bv1 = bias[c0 + 1]; }
            *(float2*)&C[(size_t)r0 * N + c0] =
                make_float2(d[am][an][0] + bv0, d[am][an][1] + bv1);
            *(float2*)&C[(size_t)(r0 + 8) * N + c0] =
                make_float2(d[am][an][2] + bv0, d[am][an][3] + bv1);
        }
    }
}

// ---------------------------------------------------------------------------
// Prep K: fp32 -> interleaved fp16 limb rows [h][k][32 groups of {hi2,lo2}].
// grid 768 x 256; unit = one (h, k, 16-d chunk).
// ---------------------------------------------------------------------------
__global__ __launch_bounds__(256) void prep_k(
    const float* __restrict__ qkv, __half* __restrict__ k16)
{
    const int u  = blockIdx.x * 256 + threadIdx.x;   // 0..196607
    const int hk = u >> 2, ch = u & 3;
    const int h = hk >> 12, k = hk & 4095;
    const float* src = qkv + (size_t)k * QKV_LD + EMB + h * HD + ch * 16;
    __half* dst = k16 + ((size_t)h * SEQ + k) * 128 + ch * 32;

    uint32_t hi[8], lo[8];
#pragma unroll
    for (int j = 0; j < 4; j++) {
        float4 v = *(const float4*)(src + j * 4);
        split_h2(v.x, v.y, hi[j * 2], lo[j * 2]);
        split_h2(v.z, v.w, hi[j * 2 + 1], lo[j * 2 + 1]);
    }
#pragma unroll
    for (int j = 0; j < 4; j++)
        *(uint4*)(dst + j * 8) = make_uint4(hi[j * 2], lo[j * 2], hi[j * 2 + 1], lo[j * 2 + 1]);
}

// ---------------------------------------------------------------------------
// Prep V: split + transpose to [h][c][k-groups {hi2,lo2}]. grid (64, 12).
// ---------------------------------------------------------------------------
__global__ __launch_bounds__(256) void prep_v(
    const float* __restrict__ qkv, __half* __restrict__ v16)
{
    __shared__ __align__(16) __half sv[2][64][80];   // 16B-aligned rows
    const int h  = blockIdx.y, kb = blockIdx.x;
    const int t  = threadIdx.x;
    {
        const int k = t >> 2, ch = t & 3;
        const float* src = qkv + (size_t)(kb * 64 + k) * QKV_LD + 2 * EMB + h * HD + ch * 16;
#pragma unroll
        for (int j = 0; j < 16; j += 2) {
            float2 v = *(const float2*)(src + j);
            __half2 a = __floats2half2_rn(v.x, v.y);
            float2 f = __half22float2(a);
            __half2 r = __floats2half2_rn(v.x - f.x, v.y - f.y);
            const int c = ch * 16 + j;
            sv[0][c][k]     = __low2half(a);
            sv[0][c + 1][k] = __high2half(a);
            sv[1][c][k]     = __low2half(r);
            sv[1][c + 1][k] = __high2half(r);
        }
    }
    __syncthreads();
    {
        const int c = t >> 2, kc = t & 3;
        __half* dst = v16 + ((size_t)h * HD + c) * (2 * SEQ) + kb * 128 + kc * 32;
#pragma unroll
        for (int j2 = 0; j2 < 4; j2++) {
            const int k0 = kc * 16 + j2 * 4;
            uint4 w = make_uint4(
                *(const uint32_t*)&sv[0][c][k0],
                *(const uint32_t*)&sv[1][c][k0],
                *(const uint32_t*)&sv[0][c][k0 + 2],
                *(const uint32_t*)&sv[1][c][k0 + 2]);
            *(uint4*)(dst + j2 * 8) = w;
        }
    }
}

// ---------------------------------------------------------------------------
// HMMA flash attention, fp16 limb split, lagged-PV, interleaved fragments:
// all smem tiles store {hi2,lo2} groups, row stride 144 halves ->
// every fragment hi/lo register pair is one LDS.64 (conflict-free).
// Q pre-scaled by 8*log2e; exp via raw ex2.approx.
// ---------------------------------------------------------------------------
#define SQI 0                      // Q  [128][144]
#define SKI (SQI + 128 * 144)      // K  [64][144]
#define SVI (SKI + 64 * 144)       // V^T[64][144]
#define SPI (SVI + 64 * 144)       // P  [128][144]
#define ATTN_HALVES (SPI + 128 * 144)         // 55296
#define ATTN_SMEM_BYTES (ATTN_HALVES * 2)     // 110592

__global__ __launch_bounds__(256, 2) void attn_hmma(
    const float* __restrict__ qkv,
    const __half* __restrict__ k16, const __half* __restrict__ v16,
    float* __restrict__ ctx)
{
    extern __shared__ __align__(16) __half sh[];
    const int tid  = threadIdx.x;
    const int lane = tid & 31;
    const int wid  = tid >> 5;
    const int grp  = lane >> 2;
    const int tg   = lane & 3;
    const int h    = blockIdx.y;
    const int q0   = blockIdx.x * 128;

    // ---- Load Q tile, scale by 8*log2e, split, store interleaved ----
#pragma unroll
    for (int f = tid; f < 512; f += 256) {
        const int row = f >> 2, ch = f & 3;
        const float* p = qkv + (size_t)(q0 + row) * QKV_LD + h * HD + ch * 16;
        uint32_t hi[8], lo[8];
#pragma unroll
        for (int j = 0; j < 4; j++) {
            float4 v = *(const float4*)(p + j * 4);
            const float sc = 8.0f * LOG2E;
            split_h2(v.x * sc, v.y * sc, hi[j * 2], lo[j * 2]);
            split_h2(v.z * sc, v.w * sc, hi[j * 2 + 1], lo[j * 2 + 1]);
        }
        __half* dst = (__half*)sh + SQI + row * 144 + ch * 32;
#pragma unroll
        for (int j = 0; j < 4; j++)
            *(uint4*)(dst + j * 8) =
                make_uint4(hi[j * 2], lo[j * 2], hi[j * 2 + 1], lo[j * 2 + 1]);
    }

    const __half* kP = k16 + (size_t)h * SEQ * 128;
    const __half* vP = v16 + (size_t)h * HD * 2 * SEQ;

    // Loader chunks: 4 per thread; chunk g -> (row, 8-half segment)
    int crow[4];
    const int cseg = tid & 15;
#pragma unroll
    for (int i = 0; i < 4; i++) crow[i] = (tid + i * 256) >> 4;

    auto sts_tile = [&](int base, int i, uint4 v) {
        *(uint4*)((__half*)sh + base + crow[i] * 144 + cseg * 8) = v;
    };

    // ---- Preload K(0) ----
    {
        uint4 kc4[4];
#pragma unroll
        for (int i = 0; i < 4; i++)
            kc4[i] = *(const uint4*)(kP + (size_t)crow[i] * 128 + cseg * 8);
#pragma unroll
        for (int i = 0; i < 4; i++) sts_tile(SKI, i, kc4[i]);
    }
    __syncthreads();

    float m0 = -1e30f, m1 = -1e30f, l0 = 0.0f, l1 = 0.0f;
    float O[8][4];
#pragma unroll
    for (int nt = 0; nt < 8; nt++)
#pragma unroll
        for (int r = 0; r < 4; r++) O[nt][r] = 0.0f;

    const int r0b = (wid * 16 + grp) * 144;     // row base (halves)
    const int r1b = r0b + 8 * 144;

    for (int it = 0; it < SEQ / 64; it++) {
        const int kt = it * 64;
        const bool pfK = (it + 1) < SEQ / 64;

        // Prefetch K(it+1) and V(it) chunks (hidden under S-MMA + PV)
        uint4 kc4[4], vc4[4];
        if (pfK) {
#pragma unroll
            for (int i = 0; i < 4; i++)
                kc4[i] = *(const uint4*)(kP + (size_t)(kt + 64 + crow[i]) * 128 + cseg * 8);
        }
#pragma unroll
        for (int i = 0; i < 4; i++)
            vc4[i] = *(const uint4*)(vP + (size_t)crow[i] * (2 * SEQ) + kt * 2 + cseg * 8);

        // ---- S = Q K^T on tile it (3 fp16 limb products) ----
        float s[8][4];
#pragma unroll
        for (int nt = 0; nt < 8; nt++)
#pragma unroll
            for (int r = 0; r < 4; r++) s[nt][r] = 0.0f;

#pragma unroll
        for (int ks = 0; ks < 4; ks++) {
            const int qg = (ks * 8 + tg) * 4;
            uint2 a0 = *(const uint2*)&sh[SQI + r0b + qg];
            uint2 a1 = *(const uint2*)&sh[SQI + r1b + qg];
            uint2 a2 = *(const uint2*)&sh[SQI + r0b + qg + 16];
            uint2 a3 = *(const uint2*)&sh[SQI + r1b + qg + 16];
            uint32_t ah[4] = {a0.x, a1.x, a2.x, a3.x};
            uint32_t al_[4] = {a0.y, a1.y, a2.y, a3.y};
#pragma unroll
            for (int nt = 0; nt < 8; nt++) {
                const int kb = SKI + (nt * 8 + grp) * 144 + qg;
                uint2 b0 = *(const uint2*)&sh[kb];
                uint2 b1 = *(const uint2*)&sh[kb + 16];
                uint32_t kh[2] = {b0.x, b1.x};
                uint32_t kl[2] = {b0.y, b1.y};
                mma_f16(s[nt], ah, kh);
                mma_f16(s[nt], al_, kh);
                mma_f16(s[nt], ah, kl);
            }
        }

        // ---- rowmax + alpha (log2 domain) ----
        float mx0 = -1e30f, mx1 = -1e30f;
#pragma unroll
        for (int nt = 0; nt < 8; nt++) {
            mx0 = fmaxf(mx0, fmaxf(s[nt][0], s[nt][1]));
            mx1 = fmaxf(mx1, fmaxf(s[nt][2], s[nt][3]));
        }
        mx0 = fmaxf(mx0, __shfl_xor_sync(0xffffffffu, mx0, 1));
        mx0 = fmaxf(mx0, __shfl_xor_sync(0xffffffffu, mx0, 2));
        mx1 = fmaxf(mx1, __shfl_xor_sync(0xffffffffu, mx1, 1));
        mx1 = fmaxf(mx1, __shfl_xor_sync(0xffffffffu, mx1, 2));

        const float mn0 = fmaxf(m0, mx0), mn1 = fmaxf(m1, mx1);
        const float al0 = ex2f(m0 - mn0), al1 = ex2f(m1 - mn1);
        m0 = mn0; m1 = mn1;

        float sum0 = 0.0f, sum1 = 0.0f;

        if (it > 0) {
            // ---- interleaved: PV(it-1) MMAs ‖ ex2(it) ----
#pragma unroll
            for (int kc = 0; kc < 4; kc++) {
                const int pg = (kc * 8 + tg) * 4;
                uint2 p0 = *(const uint2*)&sh[SPI + r0b + pg];
                uint2 p1 = *(const uint2*)&sh[SPI + r1b + pg];
                uint2 p2 = *(const uint2*)&sh[SPI + r0b + pg + 16];
                uint2 p3 = *(const uint2*)&sh[SPI + r1b + pg + 16];
                uint32_t ph[4] = {p0.x, p1.x, p2.x, p3.x};
                uint32_t pl[4] = {p0.y, p1.y, p2.y, p3.y};
#pragma unroll
                for (int nt = 0; nt < 8; nt++) {
                    const int vb = SVI + (nt * 8 + grp) * 144 + pg;
                    uint2 v0 = *(const uint2*)&sh[vb];
                    uint2 v1 = *(const uint2*)&sh[vb + 16];
                    uint32_t vh[2] = {v0.x, v1.x};
                    uint32_t vl[2] = {v0.y, v1.y};
                    mma_f16(O[nt], ph, vh);
                    mma_f16(O[nt], pl, vh);
                    mma_f16(O[nt], ph, vl);
                    if (nt < 2) {
                        const int e = kc * 2 + nt;
                        s[e][0] = ex2f(s[e][0] - mn0); sum0 += s[e][0];
                        s[e][1] = ex2f(s[e][1] - mn0); sum0 += s[e][1];
                        s[e][2] = ex2f(s[e][2] - mn1); sum1 += s[e][2];
                        s[e][3] = ex2f(s[e][3] - mn1); sum1 += s[e][3];
                    }
                }
            }
        } else {
#pragma unroll
            for (int nt = 0; nt < 8; nt++) {
                s[nt][0] = ex2f(s[nt][0] - mn0); sum0 += s[nt][0];
                s[nt][1] = ex2f(s[nt][1] - mn0); sum0 += s[nt][1];
                s[nt][2] = ex2f(s[nt][2] - mn1); sum1 += s[nt][2];
                s[nt][3] = ex2f(s[nt][3] - mn1); sum1 += s[nt][3];
            }
        }

        // ---- l update + O rescale (after PV(it-1) completed) ----
        sum0 += __shfl_xor_sync(0xffffffffu, sum0, 1);
        sum0 += __shfl_xor_sync(0xffffffffu, sum0, 2);
        sum1 += __shfl_xor_sync(0xffffffffu, sum1, 1);
        sum1 += __shfl_xor_sync(0xffffffffu, sum1, 2);
        l0 = l0 * al0 + sum0;
        l1 = l1 * al1 + sum1;

#pragma unroll
        for (int nt = 0; nt < 8; nt++) {
            O[nt][0] *= al0; O[nt][1] *= al0;
            O[nt][2] *= al1; O[nt][3] *= al1;
        }

        __syncwarp(0xffffffffu);   // PV reads of P(it-1) done before overwrite

        // ---- P(it) -> SMEM interleaved {hi,lo} (warp-private rows) ----
#pragma unroll
        for (int nt = 0; nt < 8; nt++) {
            const int g = (nt * 4 + tg) * 4;
            uint32_t hh, ll;
            split_h2(s[nt][0], s[nt][1], hh, ll);
            *(uint2*)&sh[SPI + r0b + g] = make_uint2(hh, ll);
            split_h2(s[nt][2], s[nt][3], hh, ll);
            *(uint2*)&sh[SPI + r1b + g] = make_uint2(hh, ll);
        }

        __syncthreads();   // all K(it)/V(it-1) smem reads done
        if (pfK) {
#pragma unroll
            for (int i = 0; i < 4; i++) sts_tile(SKI, i, kc4[i]);
        }
#pragma unroll
        for (int i = 0; i < 4; i++) sts_tile(SVI, i, vc4[i]);
        __syncthreads();   // K(it+1), V(it) visible
    }

    // ---- Epilogue: PV for the last tile ----
#pragma unroll
    for (int kc = 0; kc < 4; kc++) {
        const int pg = (kc * 8 + tg) * 4;
        uint2 p0 = *(const uint2*)&sh[SPI + r0b + pg];
        uint2 p1 = *(const uint2*)&sh[SPI + r1b + pg];
        uint2 p2 = *(const uint2*)&sh[SPI + r0b + pg + 16];
        uint2 p3 = *(const uint2*)&sh[SPI + r1b + pg + 16];
        uint32_t ph[4] = {p0.x, p1.x, p2.x, p3.x};
        uint32_t pl[4] = {p0.y, p1.y, p2.y, p3.y};
#pragma unroll
        for (int nt = 0; nt < 8; nt++) {
            const int vb = SVI + (nt * 8 + grp) * 144 + pg;
            uint2 v0 = *(const uint2*)&sh[vb];
            uint2 v1 = *(const uint2*)&sh[vb + 16];
            uint32_t vh[2] = {v0.x, v1.x};
            uint32_t vl[2] = {v0.y, v1.y};
            mma_f16(O[nt], ph, vh);
            mma_f16(O[nt], pl, vh);
            mma_f16(O[nt], ph, vl);
        }
    }

    // ---- Normalize and write ctx ----
    const float inv0 = 1.0f / l0, inv1 = 1.0f / l1;
    const int rr = q0 + wid * 16 + grp;
#pragma unroll
    for (int nt = 0; nt < 8; nt++) {
        const int c = h * HD + nt * 8 + tg * 2;
        *(float2*)&ctx[(size_t)rr * EMB + c] =
            make_float2(O[nt][0] * inv0, O[nt][1] * inv0);
        *(float2*)&ctx[(size_t)(rr + 8) * EMB + c] =
            make_float2(O[nt][2] * inv1, O[nt][3] * inv1);
    }
}

// ---------------------------------------------------------------------------
extern "C" void kernel_launch(void* const* d_in, const int* in_sizes, int n_in,
                              void* d_out, int out_size)
{
    (void)in_sizes; (void)n_in; (void)out_size;
    const float* x     = (const float*)d_in[0];   // [1,4096,768]
    const float* qkv_w = (const float*)d_in[1];   // [2304,768]
    const float* out_w = (const float*)d_in[2];   // [768,768]
    const float* out_b = (const float*)d_in[3];   // [768]
    float* out = (float*)d_out;                   // [1,4096,768]

    float *qkv = nullptr, *ctx = nullptr;
    __half *k16 = nullptr, *v16 = nullptr;
    cudaGetSymbolAddress((void**)&qkv, g_qkv);
    cudaGetSymbolAddress((void**)&ctx, g_ctx);
    cudaGetSymbolAddress((void**)&k16, g_k16);
    cudaGetSymbolAddress((void**)&v16, g_v16);

    // 1) QKV projection (HMMA bf16x3)
    const int smem3 = 6 * LT * (int)sizeof(__nv_bfloat16);
    cudaFuncSetAttribute(hmma_gemm_abt<3>,
                         cudaFuncAttributeMaxDynamicSharedMemorySize, smem3);
    hmma_gemm_abt<3><<<dim3(QKV_LD / 128, SEQ / 128), 256, smem3>>>(
        x, qkv_w, nullptr, qkv, SEQ, QKV_LD, EMB);

    // 2) K/V fp16 limb pre-split (interleaved fragment-friendly layout)
    prep_k<<<768, 256>>>(qkv, k16);
    prep_v<<<dim3(64, HEADS), 256>>>(qkv, v16);

    // 3) HMMA flash attention
    cudaFuncSetAttribute(attn_hmma,
                         cudaFuncAttributeMaxDynamicSharedMemorySize, ATTN_SMEM_BYTES);
    attn_hmma<<<dim3(SEQ / 128, HEADS), 256, ATTN_SMEM_BYTES>>>(qkv, k16, v16, ctx);

    // 4) Output projection + bias (HMMA bf16x2)
    const int smem2 = 4 * LT * (int)sizeof(__nv_bfloat16);
    cudaFuncSetAttribute(hmma_gemm_abt<2>,
                         cudaFuncAttributeMaxDynamicSharedMemorySize, smem2);
    hmma_gemm_abt<2><<<dim3(EMB / 128, SEQ / 128), 256, smem2>>>(
        ctx, out_w, out_b, out, SEQ, EMB, EMB);
}

// round 12
// speedup vs baseline: 1.2179x; 1.2179x over previous
#include <cuda_runtime.h>
#include <cuda_bf16.h>
#include <cuda_fp16.h>
#include <math.h>
#include <stdint.h>

#define EMB 768
#define HEADS 12
#define HD 64
#define SEQ 4096
#define QKV_LD (3 * EMB)   // 2304
#define LIMB ((size_t)HEADS * SEQ * HD)   // halves per limb plane
#define LOG2E 1.4426950408889634f

// Scratch (static device globals — no allocation)
__device__ __align__(16) float g_qkv[(size_t)SEQ * QKV_LD];  // [l][3*emb] : Q|K|V
__device__ __align__(16) float g_ctx[(size_t)SEQ * EMB];     // [l][h*64 + c]
__device__ __align__(16) __half g_k16[2 * HEADS * SEQ * HD]; // [limb][h][k][d]
__device__ __align__(16) __half g_v16[2 * HEADS * SEQ * HD]; // [limb][h][c][k]

// ---------------------------------------------------------------------------
// HMMA helpers (mma.sync — supported on base sm_103 target)
// ---------------------------------------------------------------------------
__device__ __forceinline__ void mma_bf16(float* d, const uint32_t* a, const uint32_t* b) {
    asm volatile(
        "mma.sync.aligned.m16n8k16.row.col.f32.bf16.bf16.f32 "
        "{%0,%1,%2,%3}, {%4,%5,%6,%7}, {%8,%9}, {%0,%1,%2,%3};"
        : "+f"(d[0]), "+f"(d[1]), "+f"(d[2]), "+f"(d[3])
        : "r"(a[0]), "r"(a[1]), "r"(a[2]), "r"(a[3]), "r"(b[0]), "r"(b[1]));
}
__device__ __forceinline__ void mma_f16(float* d, const uint32_t* a, const uint32_t* b) {
    asm volatile(
        "mma.sync.aligned.m16n8k16.row.col.f32.f16.f16.f32 "
        "{%0,%1,%2,%3}, {%4,%5,%6,%7}, {%8,%9}, {%0,%1,%2,%3};"
        : "+f"(d[0]), "+f"(d[1]), "+f"(d[2]), "+f"(d[3])
        : "r"(a[0]), "r"(a[1]), "r"(a[2]), "r"(a[3]), "r"(b[0]), "r"(b[1]));
}
__device__ __forceinline__ uint32_t h2bits(__half2 h) { return *(uint32_t*)&h; }
__device__ __forceinline__ float ex2f(float x) {
    float r; asm("ex2.approx.ftz.f32 %0, %1;" : "=f"(r) : "f"(x)); return r;
}

// fp32 pair -> fp16 hi/lo limbs (packed f16x2: x -> low half)
__device__ __forceinline__ void split_h2(float x, float y, uint32_t& hi, uint32_t& lo) {
    __half2 h = __floats2half2_rn(x, y);
    float2 f = __half22float2(h);
    __half2 l = __floats2half2_rn(x - f.x, y - f.y);
    hi = h2bits(h);
    lo = h2bits(l);
}

// fp32 pair -> bf16 limb split (for projection GEMMs)
__device__ __forceinline__ void split_pair_bf(
    float x, float y, uint32_t& h, uint32_t& m, uint32_t& l, bool want3)
{
    __nv_bfloat162 hb = __float22bfloat162_rn(make_float2(x, y));
    float2 hf = __bfloat1622float2(hb);
    float rx = x - hf.x, ry = y - hf.y;
    __nv_bfloat162 mb = __float22bfloat162_rn(make_float2(rx, ry));
    h = *(uint32_t*)&hb;
    m = *(uint32_t*)&mb;
    if (want3) {
        float2 mf = __bfloat1622float2(mb);
        __nv_bfloat162 lb = __float22bfloat162_rn(make_float2(rx - mf.x, ry - mf.y));
        l = *(uint32_t*)&lb;
    } else {
        l = 0;
    }
}

// ---------------------------------------------------------------------------
// HMMA GEMM: C[M,N] = A[M,K] @ B[N,K]^T (+bias), fp32 via bf16 limb split.
// (unchanged — passing; 2 CTAs/SM, tensor 62%)
// ---------------------------------------------------------------------------
#define LT (128 * 40)   // bf16 elements per limb tile

template<int NSPLIT>
__global__ __launch_bounds__(256, 2) void hmma_gemm_abt(
    const float* __restrict__ A, const float* __restrict__ B,
    const float* __restrict__ bias, float* __restrict__ C,
    int M, int N, int K)
{
    extern __shared__ __align__(16) char smem[];
    __nv_bfloat16* As = (__nv_bfloat16*)smem;
    __nv_bfloat16* Bs = As + NSPLIT * LT;

    const int tid  = threadIdx.x;
    const int lane = tid & 31;
    const int wid  = tid >> 5;
    const int wm   = wid >> 2;
    const int wn   = wid & 3;
    const int grp  = lane >> 2;
    const int tg   = lane & 3;
    const int bm0  = blockIdx.y * 128;
    const int bn0  = blockIdx.x * 128;

    float d[4][4][4];
#pragma unroll
    for (int am = 0; am < 4; am++)
#pragma unroll
        for (int an = 0; an < 4; an++)
#pragma unroll
            for (int r = 0; r < 4; r++) d[am][an][r] = 0.0f;

    const int NPR = (NSPLIT == 3) ? 6 : 3;
    const int PA[6] = {0, 0, 1, 0, 2, 1};
    const int PB[6] = {0, 1, 0, 2, 0, 1};

    for (int k0 = 0; k0 < K; k0 += 32) {
        __syncthreads();
#pragma unroll
        for (int half = 0; half < 2; half++) {
            const float* src = half ? (B + (size_t)bn0 * K) : (A + (size_t)bm0 * K);
            __nv_bfloat16* dst = half ? Bs : As;
#pragma unroll
            for (int it = 0; it < 2; it++) {
                const int f   = tid + it * 256;
                const int row = f >> 2;
                const int c8  = f & 3;
                const float* p = src + (size_t)row * K + k0 + c8 * 8;
                float4 v0 = *(const float4*)p;
                float4 v1 = *(const float4*)(p + 4);
                uint32_t h[4], m[4], l[4];
                split_pair_bf(v0.x, v0.y, h[0], m[0], l[0], NSPLIT == 3);
                split_pair_bf(v0.z, v0.w, h[1], m[1], l[1], NSPLIT == 3);
                split_pair_bf(v1.x, v1.y, h[2], m[2], l[2], NSPLIT == 3);
                split_pair_bf(v1.z, v1.w, h[3], m[3], l[3], NSPLIT == 3);
                const int base = row * 40 + c8 * 8;
#pragma unroll
                for (int j = 0; j < 4; j++) {
                    *(uint32_t*)&dst[0 * LT + base + j * 2] = h[j];
                    *(uint32_t*)&dst[1 * LT + base + j * 2] = m[j];
                    if (NSPLIT == 3)
                        *(uint32_t*)&dst[2 * LT + base + j * 2] = l[j];
                }
            }
        }
        __syncthreads();

#pragma unroll
        for (int ks = 0; ks < 2; ks++) {
#pragma unroll
            for (int p = 0; p < NPR; p++) {
                const int la = PA[p], lb = PB[p];
                uint32_t afr[4][4];
#pragma unroll
                for (int am = 0; am < 4; am++) {
                    const __nv_bfloat16* ap =
                        As + la * LT + (wm * 64 + am * 16 + grp) * 40 + ks * 16 + tg * 2;
                    afr[am][0] = *(const uint32_t*)ap;
                    afr[am][1] = *(const uint32_t*)(ap + 8 * 40);
                    afr[am][2] = *(const uint32_t*)(ap + 8);
                    afr[am][3] = *(const uint32_t*)(ap + 8 * 40 + 8);
                }
#pragma unroll
                for (int an = 0; an < 4; an++) {
                    const __nv_bfloat16* bp =
                        Bs + lb * LT + (wn * 32 + an * 8 + grp) * 40 + ks * 16 + tg * 2;
                    uint32_t bfr[2];
                    bfr[0] = *(const uint32_t*)bp;
                    bfr[1] = *(const uint32_t*)(bp + 8);
#pragma unroll
                    for (int am = 0; am < 4; am++)
                        mma_bf16(d[am][an], afr[am], bfr);
                }
            }
        }
    }

#pragma unroll
    for (int am = 0; am < 4; am++) {
        const int r0 = bm0 + wm * 64 + am * 16 + grp;
#pragma unroll
        for (int an = 0; an < 4; an++) {
            const int c0 = bn0 + wn * 32 + an * 8 + tg * 2;
            float bv0 = 0.0f, bv1 = 0.0f;
            if (bias) { bv0 = bias[c0]; bv1 = bias[c0 + 1]; }
            *(float2*)&C[(size_t)r0 * N + c0] =
                make_float2(d[am][an][0] + bv0, d[am][an][1] + bv1);
            *(float2*)&C[(size_t)(r0 + 8) * N + c0] =
                make_float2(d[am][an][2] + bv0, d[am][an][3] + bv1);
        }
    }
}

// ---------------------------------------------------------------------------
// Prep K: fp32 -> fp16 hi/lo limbs, layout [limb][h][k][d]. (round-10 proven)
// ---------------------------------------------------------------------------
__global__ __launch_bounds__(256) void prep_k(
    const float* __restrict__ qkv, __half* __restrict__ k16)
{
    const int u  = blockIdx.x * 256 + threadIdx.x;   // 0..196607
    const int hk = u >> 2, ch = u & 3;
    const int h = hk >> 12, k = hk & 4095;
    const float* src = qkv + (size_t)k * QKV_LD + EMB + h * HD + ch * 16;
    __half* dh = k16 + ((size_t)h * SEQ + k) * HD + ch * 16;

    uint32_t hi[8], lo[8];
#pragma unroll
    for (int j = 0; j < 4; j++) {
        float4 v = *(const float4*)(src + j * 4);
        split_h2(v.x, v.y, hi[j * 2], lo[j * 2]);
        split_h2(v.z, v.w, hi[j * 2 + 1], lo[j * 2 + 1]);
    }
    *(uint4*)dh       = make_uint4(hi[0], hi[1], hi[2], hi[3]);
    *(uint4*)(dh + 8) = make_uint4(hi[4], hi[5], hi[6], hi[7]);
    __half* dl = dh + LIMB;
    *(uint4*)dl       = make_uint4(lo[0], lo[1], lo[2], lo[3]);
    *(uint4*)(dl + 8) = make_uint4(lo[4], lo[5], lo[6], lo[7]);
}

// ---------------------------------------------------------------------------
// Prep V: split + transpose to [limb][h][c][k]. (round-10 proven)
// ---------------------------------------------------------------------------
__global__ __launch_bounds__(256) void prep_v(
    const float* __restrict__ qkv, __half* __restrict__ v16)
{
    __shared__ __align__(16) __half sv[2][64][80];
    const int h  = blockIdx.y, kb = blockIdx.x;
    const int t  = threadIdx.x;
    {
        const int k = t >> 2, ch = t & 3;
        const float* src = qkv + (size_t)(kb * 64 + k) * QKV_LD + 2 * EMB + h * HD + ch * 16;
#pragma unroll
        for (int j = 0; j < 16; j += 2) {
            float2 v = *(const float2*)(src + j);
            __half2 a = __floats2half2_rn(v.x, v.y);
            float2 f = __half22float2(a);
            __half2 r = __floats2half2_rn(v.x - f.x, v.y - f.y);
            const int c = ch * 16 + j;
            sv[0][c][k]     = __low2half(a);
            sv[0][c + 1][k] = __high2half(a);
            sv[1][c][k]     = __low2half(r);
            sv[1][c + 1][k] = __high2half(r);
        }
    }
    __syncthreads();
    {
        const int c = t >> 2, kc = t & 3;
        __half* dst = v16 + ((size_t)h * HD + c) * SEQ + kb * 64 + kc * 16;
#pragma unroll
        for (int j = 0; j < 2; j++) {
            *(uint4*)(dst + j * 8)        = *(const uint4*)&sv[0][c][kc * 16 + j * 8];
            *(uint4*)(dst + LIMB + j * 8) = *(const uint4*)&sv[1][c][kc * 16 + j * 8];
        }
    }
}

// ---------------------------------------------------------------------------
// HMMA flash attention (round-10 inner loop, repartitioned):
// q-tile 64, 128 threads (4 warps), 3 CTAs/SM -> 444 slots for 768 blocks
// (packing 65% -> 86%). Q pre-scaled by 8*log2e; exp via ex2.approx.
// ---------------------------------------------------------------------------
#define SQH 0                    // Q hi  [64][72]
#define SQL (SQH + 64 * 72)      // Q lo
#define SKH (SQL + 64 * 72)      // K hi  [64 key][72 d]
#define SKL (SKH + 64 * 72)      // K lo
#define SVH (SKL + 64 * 72)      // V^T hi [64 c][72 k]
#define SVL (SVH + 64 * 72)      // V^T lo
#define SPH (SVL + 64 * 72)      // P hi  [64 q][72 k]
#define SPL (SPH + 64 * 72)      // P lo
#define ATTN_HALVES (SPL + 64 * 72)           // 36864
#define ATTN_SMEM_BYTES (ATTN_HALVES * 2)     // 73728

__global__ __launch_bounds__(128, 3) void attn_hmma(
    const float* __restrict__ qkv,
    const __half* __restrict__ k16, const __half* __restrict__ v16,
    float* __restrict__ ctx)
{
    extern __shared__ __align__(16) __half sh[];
    const int tid  = threadIdx.x;
    const int lane = tid & 31;
    const int wid  = tid >> 5;           // 0..3
    const int grp  = lane >> 2;
    const int tg   = lane & 3;
    const int h    = blockIdx.y;
    const int q0   = blockIdx.x * 64;

    // ---- Load Q tile (64 rows), scale by 8*log2e, split into fp16 limbs ----
#pragma unroll
    for (int f = tid; f < 256; f += 128) {
        const int row = f >> 2, ch = f & 3;
        const float* p = qkv + (size_t)(q0 + row) * QKV_LD + h * HD + ch * 16;
        uint32_t hi[8], lo[8];
#pragma unroll
        for (int j = 0; j < 4; j++) {
            float4 v = *(const float4*)(p + j * 4);
            const float sc = 8.0f * LOG2E;
            split_h2(v.x * sc, v.y * sc, hi[j * 2], lo[j * 2]);
            split_h2(v.z * sc, v.w * sc, hi[j * 2 + 1], lo[j * 2 + 1]);
        }
        const int o = row * 72 + ch * 16;
        *(uint4*)&sh[SQH + o]     = make_uint4(hi[0], hi[1], hi[2], hi[3]);
        *(uint4*)&sh[SQH + o + 8] = make_uint4(hi[4], hi[5], hi[6], hi[7]);
        *(uint4*)&sh[SQL + o]     = make_uint4(lo[0], lo[1], lo[2], lo[3]);
        *(uint4*)&sh[SQL + o + 8] = make_uint4(lo[4], lo[5], lo[6], lo[7]);
    }

    const __half* kP = k16 + (size_t)h * SEQ * HD;
    const __half* vP = v16 + (size_t)h * HD * SEQ;

    // Chunk decode: g = tid + i*128 -> (limb, row, 8-half segment); 8 chunks.
    int clt[8], crow[8], cseg[8];
#pragma unroll
    for (int i = 0; i < 8; i++) {
        const int g = tid + i * 128;
        clt[i]  = g >> 9;
        crow[i] = (g >> 3) & 63;
        cseg[i] = g & 7;
    }

    auto sts_chunk = [&](int base_h, int base_l, int i, uint4 v) {
        const int off = (base_h + (clt[i] ? (base_l - base_h) : 0))
                        + crow[i] * 72 + cseg[i] * 8;
        *(uint2*)&sh[off]     = make_uint2(v.x, v.y);
        *(uint2*)&sh[off + 4] = make_uint2(v.z, v.w);
    };

    // ---- Preload K(0) ----
    {
        uint4 kc4[8];
#pragma unroll
        for (int i = 0; i < 8; i++)
            kc4[i] = *(const uint4*)(kP + clt[i] * LIMB + (size_t)crow[i] * HD + cseg[i] * 8);
#pragma unroll
        for (int i = 0; i < 8; i++) sts_chunk(SKH, SKL, i, kc4[i]);
    }
    __syncthreads();

    float m0 = -1e30f, m1 = -1e30f, l0 = 0.0f, l1 = 0.0f;
    float O[8][4];
#pragma unroll
    for (int nt = 0; nt < 8; nt++)
#pragma unroll
        for (int r = 0; r < 4; r++) O[nt][r] = 0.0f;

    const int qrow = (wid * 16 + grp) * 72 + tg * 2;   // Q-row / P-row base

    for (int it = 0; it < SEQ / 64; it++) {
        const int kt = it * 64;
        const bool pfK = (it + 1) < SEQ / 64;

        // Prefetch K(it+1) and V(it) limb chunks (hidden under S-MMA + PV)
        uint4 kc4[8], vc4[8];
        if (pfK) {
#pragma unroll
            for (int i = 0; i < 8; i++)
                kc4[i] = *(const uint4*)(kP + clt[i] * LIMB
                             + (size_t)(kt + 64 + crow[i]) * HD + cseg[i] * 8);
        }
#pragma unroll
        for (int i = 0; i < 8; i++)
            vc4[i] = *(const uint4*)(vP + clt[i] * LIMB
                         + (size_t)crow[i] * SEQ + kt + cseg[i] * 8);

        // ---- S = Q K^T on tile it (3 fp16 limb products) ----
        float s[8][4];
#pragma unroll
        for (int nt = 0; nt < 8; nt++)
#pragma unroll
            for (int r = 0; r < 4; r++) s[nt][r] = 0.0f;

#pragma unroll
        for (int ks = 0; ks < 4; ks++) {
            const int qa = qrow + ks * 16;
            uint32_t ah[4], al_[4];
            ah[0] = *(const uint32_t*)&sh[SQH + qa];
            ah[1] = *(const uint32_t*)&sh[SQH + qa + 8 * 72];
            ah[2] = *(const uint32_t*)&sh[SQH + qa + 8];
            ah[3] = *(const uint32_t*)&sh[SQH + qa + 8 * 72 + 8];
            al_[0] = *(const uint32_t*)&sh[SQL + qa];
            al_[1] = *(const uint32_t*)&sh[SQL + qa + 8 * 72];
            al_[2] = *(const uint32_t*)&sh[SQL + qa + 8];
            al_[3] = *(const uint32_t*)&sh[SQL + qa + 8 * 72 + 8];
#pragma unroll
            for (int nt = 0; nt < 8; nt++) {
                const int ka = (nt * 8 + grp) * 72 + ks * 16 + tg * 2;
                uint32_t kh[2], kl[2];
                kh[0] = *(const uint32_t*)&sh[SKH + ka];
                kh[1] = *(const uint32_t*)&sh[SKH + ka + 8];
                kl[0] = *(const uint32_t*)&sh[SKL + ka];
                kl[1] = *(const uint32_t*)&sh[SKL + ka + 8];
                mma_f16(s[nt], ah, kh);
                mma_f16(s[nt], al_, kh);
                mma_f16(s[nt], ah, kl);
            }
        }

        // ---- rowmax + alpha (log2 domain) ----
        float mx0 = -1e30f, mx1 = -1e30f;
#pragma unroll
        for (int nt = 0; nt < 8; nt++) {
            mx0 = fmaxf(mx0, fmaxf(s[nt][0], s[nt][1]));
            mx1 = fmaxf(mx1, fmaxf(s[nt][2], s[nt][3]));
        }
        mx0 = fmaxf(mx0, __shfl_xor_sync(0xffffffffu, mx0, 1));
        mx0 = fmaxf(mx0, __shfl_xor_sync(0xffffffffu, mx0, 2));
        mx1 = fmaxf(mx1, __shfl_xor_sync(0xffffffffu, mx1, 1));
        mx1 = fmaxf(mx1, __shfl_xor_sync(0xffffffffu, mx1, 2));

        const float mn0 = fmaxf(m0, mx0), mn1 = fmaxf(m1, mx1);
        const float al0 = ex2f(m0 - mn0), al1 = ex2f(m1 - mn1);
        m0 = mn0; m1 = mn1;

        float sum0 = 0.0f, sum1 = 0.0f;

        if (it > 0) {
            // ---- interleaved: PV(it-1) MMAs ‖ ex2(it) ----
#pragma unroll
            for (int kc = 0; kc < 4; kc++) {
                const int pa = qrow + kc * 16;
                uint32_t ph[4], pl[4];
                ph[0] = *(const uint32_t*)&sh[SPH + pa];
                ph[1] = *(const uint32_t*)&sh[SPH + pa + 8 * 72];
                ph[2] = *(const uint32_t*)&sh[SPH + pa + 8];
                ph[3] = *(const uint32_t*)&sh[SPH + pa + 8 * 72 + 8];
                pl[0] = *(const uint32_t*)&sh[SPL + pa];
                pl[1] = *(const uint32_t*)&sh[SPL + pa + 8 * 72];
                pl[2] = *(const uint32_t*)&sh[SPL + pa + 8];
                pl[3] = *(const uint32_t*)&sh[SPL + pa + 8 * 72 + 8];
#pragma unroll
                for (int nt = 0; nt < 8; nt++) {
                    const int va = (nt * 8 + grp) * 72 + kc * 16 + tg * 2;
                    uint32_t vh[2], vl[2];
                    vh[0] = *(const uint32_t*)&sh[SVH + va];
                    vh[1] = *(const uint32_t*)&sh[SVH + va + 8];
                    vl[0] = *(const uint32_t*)&sh[SVL + va];
                    vl[1] = *(const uint32_t*)&sh[SVL + va + 8];
                    mma_f16(O[nt], ph, vh);
                    mma_f16(O[nt], pl, vh);
                    mma_f16(O[nt], ph, vl);
                    if (nt < 2) {
                        const int e = kc * 2 + nt;
                        s[e][0] = ex2f(s[e][0] - mn0); sum0 += s[e][0];
                        s[e][1] = ex2f(s[e][1] - mn0); sum0 += s[e][1];
                        s[e][2] = ex2f(s[e][2] - mn1); sum1 += s[e][2];
                        s[e][3] = ex2f(s[e][3] - mn1); sum1 += s[e][3];
                    }
                }
            }
        } else {
#pragma unroll
            for (int nt = 0; nt < 8; nt++) {
                s[nt][0] = ex2f(s[nt][0] - mn0); sum0 += s[nt][0];
                s[nt][1] = ex2f(s[nt][1] - mn0); sum0 += s[nt][1];
                s[nt][2] = ex2f(s[nt][2] - mn1); sum1 += s[nt][2];
                s[nt][3] = ex2f(s[nt][3] - mn1); sum1 += s[nt][3];
            }
        }

        // ---- l update + O rescale (after PV(it-1) completed) ----
        sum0 += __shfl_xor_sync(0xffffffffu, sum0, 1);
        sum0 += __shfl_xor_sync(0xffffffffu, sum0, 2);
        sum1 += __shfl_xor_sync(0xffffffffu, sum1, 1);
        sum1 += __shfl_xor_sync(0xffffffffu, sum1, 2);
        l0 = l0 * al0 + sum0;
        l1 = l1 * al1 + sum1;

#pragma unroll
        for (int nt = 0; nt < 8; nt++) {
            O[nt][0] *= al0; O[nt][1] *= al0;
            O[nt][2] *= al1; O[nt][3] *= al1;
        }

        __syncwarp(0xffffffffu);   // PV reads of P(it-1) done before overwrite

        // ---- P(it) -> SMEM fp16 limbs (warp-private rows) ----
#pragma unroll
        for (int nt = 0; nt < 8; nt++) {
            uint32_t hh, ll;
            const int pa0 = qrow + nt * 8;
            split_h2(s[nt][0], s[nt][1], hh, ll);
            *(uint32_t*)&sh[SPH + pa0] = hh;
            *(uint32_t*)&sh[SPL + pa0] = ll;
            split_h2(s[nt][2], s[nt][3], hh, ll);
            *(uint32_t*)&sh[SPH + pa0 + 8 * 72] = hh;
            *(uint32_t*)&sh[SPL + pa0 + 8 * 72] = ll;
        }

        __syncthreads();   // all K(it)/V(it-1) smem reads done
        if (pfK) {
#pragma unroll
            for (int i = 0; i < 8; i++) sts_chunk(SKH, SKL, i, kc4[i]);
        }
#pragma unroll
        for (int i = 0; i < 8; i++) sts_chunk(SVH, SVL, i, vc4[i]);
        __syncthreads();   // K(it+1), V(it) visible
    }

    // ---- Epilogue: PV for the last tile ----
#pragma unroll
    for (int kc = 0; kc < 4; kc++) {
        const int pa = qrow + kc * 16;
        uint32_t ph[4], pl[4];
        ph[0] = *(const uint32_t*)&sh[SPH + pa];
        ph[1] = *(const uint32_t*)&sh[SPH + pa + 8 * 72];
        ph[2] = *(const uint32_t*)&sh[SPH + pa + 8];
        ph[3] = *(const uint32_t*)&sh[SPH + pa + 8 * 72 + 8];
        pl[0] = *(const uint32_t*)&sh[SPL + pa];
        pl[1] = *(const uint32_t*)&sh[SPL + pa + 8 * 72];
        pl[2] = *(const uint32_t*)&sh[SPL + pa + 8];
        pl[3] = *(const uint32_t*)&sh[SPL + pa + 8 * 72 + 8];
#pragma unroll
        for (int nt = 0; nt < 8; nt++) {
            const int va = (nt * 8 + grp) * 72 + kc * 16 + tg * 2;
            uint32_t vh[2], vl[2];
            vh[0] = *(const uint32_t*)&sh[SVH + va];
            vh[1] = *(const uint32_t*)&sh[SVH + va + 8];
            vl[0] = *(const uint32_t*)&sh[SVL + va];
            vl[1] = *(const uint32_t*)&sh[SVL + va + 8];
            mma_f16(O[nt], ph, vh);
            mma_f16(O[nt], pl, vh);
            mma_f16(O[nt], ph, vl);
        }
    }

    // ---- Normalize and write ctx ----
    const float inv0 = 1.0f / l0, inv1 = 1.0f / l1;
    const int r0 = q0 + wid * 16 + grp;
#pragma unroll
    for (int nt = 0; nt < 8; nt++) {
        const int c = h * HD + nt * 8 + tg * 2;
        *(float2*)&ctx[(size_t)r0 * EMB + c] =
            make_float2(O[nt][0] * inv0, O[nt][1] * inv0);
        *(float2*)&ctx[(size_t)(r0 + 8) * EMB + c] =
            make_float2(O[nt][2] * inv1, O[nt][3] * inv1);
    }
}

// ---------------------------------------------------------------------------
extern "C" void kernel_launch(void* const* d_in, const int* in_sizes, int n_in,
                              void* d_out, int out_size)
{
    (void)in_sizes; (void)n_in; (void)out_size;
    const float* x     = (const float*)d_in[0];   // [1,4096,768]
    const float* qkv_w = (const float*)d_in[1];   // [2304,768]
    const float* out_w = (const float*)d_in[2];   // [768,768]
    const float* out_b = (const float*)d_in[3];   // [768]
    float* out = (float*)d_out;                   // [1,4096,768]

    float *qkv = nullptr, *ctx = nullptr;
    __half *k16 = nullptr, *v16 = nullptr;
    cudaGetSymbolAddress((void**)&qkv, g_qkv);
    cudaGetSymbolAddress((void**)&ctx, g_ctx);
    cudaGetSymbolAddress((void**)&k16, g_k16);
    cudaGetSymbolAddress((void**)&v16, g_v16);

    // 1) QKV projection (HMMA bf16x3)
    const int smem3 = 6 * LT * (int)sizeof(__nv_bfloat16);
    cudaFuncSetAttribute(hmma_gemm_abt<3>,
                         cudaFuncAttributeMaxDynamicSharedMemorySize, smem3);
    hmma_gemm_abt<3><<<dim3(QKV_LD / 128, SEQ / 128), 256, smem3>>>(
        x, qkv_w, nullptr, qkv, SEQ, QKV_LD, EMB);

    // 2) K/V fp16 limb pre-split
    prep_k<<<768, 256>>>(qkv, k16);
    prep_v<<<dim3(64, HEADS), 256>>>(qkv, v16);

    // 3) HMMA flash attention (64-q tiles, 128 thr, 3 CTAs/SM)
    cudaFuncSetAttribute(attn_hmma,
                         cudaFuncAttributeMaxDynamicSharedMemorySize, ATTN_SMEM_BYTES);
    attn_hmma<<<dim3(SEQ / 64, HEADS), 128, ATTN_SMEM_BYTES>>>(qkv, k16, v16, ctx);

    // 4) Output projection + bias (HMMA bf16x2)
    const int smem2 = 4 * LT * (int)sizeof(__nv_bfloat16);
    cudaFuncSetAttribute(hmma_gemm_abt<2>,
                         cudaFuncAttributeMaxDynamicSharedMemorySize, smem2);
    hmma_gemm_abt<2><<<dim3(EMB / 128, SEQ / 128), 256, smem2>>>(
        ctx, out_w, out_b, out, SEQ, EMB, EMB);
}

// round 13
// speedup vs baseline: 1.3403x; 1.1004x over previous
#include <cuda_runtime.h>
#include <cuda_bf16.h>
#include <cuda_fp16.h>
#include <math.h>
#include <stdint.h>

#define EMB 768
#define HEADS 12
#define HD 64
#define SEQ 4096
#define QKV_LD (3 * EMB)   // 2304
#define LIMB ((size_t)HEADS * SEQ * HD)   // halves per limb plane
#define LOG2E 1.4426950408889634f
#define NSPLIT_K 3

// Scratch (static device globals — no allocation)
__device__ __align__(16) float g_qkv[(size_t)SEQ * QKV_LD];  // [l][3*emb] : Q|K|V
__device__ __align__(16) float g_ctx[(size_t)SEQ * EMB];     // [l][h*64 + c]
__device__ __align__(16) __half g_k16[2 * HEADS * SEQ * HD]; // [limb][h][k][d]
__device__ __align__(16) __half g_v16[2 * HEADS * SEQ * HD]; // [limb][h][c][k]
__device__ __align__(16) float g_part[(size_t)NSPLIT_K * SEQ * EMB];      // partial O
__device__ __align__(16) float g_ml[(size_t)NSPLIT_K * HEADS * SEQ * 2]; // (m,l)

// ---------------------------------------------------------------------------
// HMMA helpers (mma.sync — supported on base sm_103 target)
// ---------------------------------------------------------------------------
__device__ __forceinline__ void mma_bf16(float* d, const uint32_t* a, const uint32_t* b) {
    asm volatile(
        "mma.sync.aligned.m16n8k16.row.col.f32.bf16.bf16.f32 "
        "{%0,%1,%2,%3}, {%4,%5,%6,%7}, {%8,%9}, {%0,%1,%2,%3};"
        : "+f"(d[0]), "+f"(d[1]), "+f"(d[2]), "+f"(d[3])
        : "r"(a[0]), "r"(a[1]), "r"(a[2]), "r"(a[3]), "r"(b[0]), "r"(b[1]));
}
__device__ __forceinline__ void mma_f16(float* d, const uint32_t* a, const uint32_t* b) {
    asm volatile(
        "mma.sync.aligned.m16n8k16.row.col.f32.f16.f16.f32 "
        "{%0,%1,%2,%3}, {%4,%5,%6,%7}, {%8,%9}, {%0,%1,%2,%3};"
        : "+f"(d[0]), "+f"(d[1]), "+f"(d[2]), "+f"(d[3])
        : "r"(a[0]), "r"(a[1]), "r"(a[2]), "r"(a[3]), "r"(b[0]), "r"(b[1]));
}
__device__ __forceinline__ uint32_t h2bits(__half2 h) { return *(uint32_t*)&h; }
__device__ __forceinline__ float ex2f(float x) {
    float r; asm("ex2.approx.ftz.f32 %0, %1;" : "=f"(r) : "f"(x)); return r;
}

// fp32 pair -> fp16 hi/lo limbs (packed f16x2: x -> low half)
__device__ __forceinline__ void split_h2(float x, float y, uint32_t& hi, uint32_t& lo) {
    __half2 h = __floats2half2_rn(x, y);
    float2 f = __half22float2(h);
    __half2 l = __floats2half2_rn(x - f.x, y - f.y);
    hi = h2bits(h);
    lo = h2bits(l);
}

// fp32 pair -> bf16 limb split (for projection GEMMs)
__device__ __forceinline__ void split_pair_bf(
    float x, float y, uint32_t& h, uint32_t& m, uint32_t& l, bool want3)
{
    __nv_bfloat162 hb = __float22bfloat162_rn(make_float2(x, y));
    float2 hf = __bfloat1622float2(hb);
    float rx = x - hf.x, ry = y - hf.y;
    __nv_bfloat162 mb = __float22bfloat162_rn(make_float2(rx, ry));
    h = *(uint32_t*)&hb;
    m = *(uint32_t*)&mb;
    if (want3) {
        float2 mf = __bfloat1622float2(mb);
        __nv_bfloat162 lb = __float22bfloat162_rn(make_float2(rx - mf.x, ry - mf.y));
        l = *(uint32_t*)&lb;
    } else {
        l = 0;
    }
}

// ---------------------------------------------------------------------------
// HMMA GEMM: C[M,N] = A[M,K] @ B[N,K]^T (+bias), fp32 via bf16 limb split.
// (unchanged — passing; 2 CTAs/SM, tensor 62%)
// ---------------------------------------------------------------------------
#define LT (128 * 40)   // bf16 elements per limb tile

template<int NSPLIT>
__global__ __launch_bounds__(256, 2) void hmma_gemm_abt(
    const float* __restrict__ A, const float* __restrict__ B,
    const float* __restrict__ bias, float* __restrict__ C,
    int M, int N, int K)
{
    extern __shared__ __align__(16) char smem[];
    __nv_bfloat16* As = (__nv_bfloat16*)smem;
    __nv_bfloat16* Bs = As + NSPLIT * LT;

    const int tid  = threadIdx.x;
    const int lane = tid & 31;
    const int wid  = tid >> 5;
    const int wm   = wid >> 2;
    const int wn   = wid & 3;
    const int grp  = lane >> 2;
    const int tg   = lane & 3;
    const int bm0  = blockIdx.y * 128;
    const int bn0  = blockIdx.x * 128;

    float d[4][4][4];
#pragma unroll
    for (int am = 0; am < 4; am++)
#pragma unroll
        for (int an = 0; an < 4; an++)
#pragma unroll
            for (int r = 0; r < 4; r++) d[am][an][r] = 0.0f;

    const int NPR = (NSPLIT == 3) ? 6 : 3;
    const int PA[6] = {0, 0, 1, 0, 2, 1};
    const int PB[6] = {0, 1, 0, 2, 0, 1};

    for (int k0 = 0; k0 < K; k0 += 32) {
        __syncthreads();
#pragma unroll
        for (int half = 0; half < 2; half++) {
            const float* src = half ? (B + (size_t)bn0 * K) : (A + (size_t)bm0 * K);
            __nv_bfloat16* dst = half ? Bs : As;
#pragma unroll
            for (int it = 0; it < 2; it++) {
                const int f   = tid + it * 256;
                const int row = f >> 2;
                const int c8  = f & 3;
                const float* p = src + (size_t)row * K + k0 + c8 * 8;
                float4 v0 = *(const float4*)p;
                float4 v1 = *(const float4*)(p + 4);
                uint32_t h[4], m[4], l[4];
                split_pair_bf(v0.x, v0.y, h[0], m[0], l[0], NSPLIT == 3);
                split_pair_bf(v0.z, v0.w, h[1], m[1], l[1], NSPLIT == 3);
                split_pair_bf(v1.x, v1.y, h[2], m[2], l[2], NSPLIT == 3);
                split_pair_bf(v1.z, v1.w, h[3], m[3], l[3], NSPLIT == 3);
                const int base = row * 40 + c8 * 8;
#pragma unroll
                for (int j = 0; j < 4; j++) {
                    *(uint32_t*)&dst[0 * LT + base + j * 2] = h[j];
                    *(uint32_t*)&dst[1 * LT + base + j * 2] = m[j];
                    if (NSPLIT == 3)
                        *(uint32_t*)&dst[2 * LT + base + j * 2] = l[j];
                }
            }
        }
        __syncthreads();

#pragma unroll
        for (int ks = 0; ks < 2; ks++) {
#pragma unroll
            for (int p = 0; p < NPR; p++) {
                const int la = PA[p], lb = PB[p];
                uint32_t afr[4][4];
#pragma unroll
                for (int am = 0; am < 4; am++) {
                    const __nv_bfloat16* ap =
                        As + la * LT + (wm * 64 + am * 16 + grp) * 40 + ks * 16 + tg * 2;
                    afr[am][0] = *(const uint32_t*)ap;
                    afr[am][1] = *(const uint32_t*)(ap + 8 * 40);
                    afr[am][2] = *(const uint32_t*)(ap + 8);
                    afr[am][3] = *(const uint32_t*)(ap + 8 * 40 + 8);
                }
#pragma unroll
                for (int an = 0; an < 4; an++) {
                    const __nv_bfloat16* bp =
                        Bs + lb * LT + (wn * 32 + an * 8 + grp) * 40 + ks * 16 + tg * 2;
                    uint32_t bfr[2];
                    bfr[0] = *(const uint32_t*)bp;
                    bfr[1] = *(const uint32_t*)(bp + 8);
#pragma unroll
                    for (int am = 0; am < 4; am++)
                        mma_bf16(d[am][an], afr[am], bfr);
                }
            }
        }
    }

#pragma unroll
    for (int am = 0; am < 4; am++) {
        const int r0 = bm0 + wm * 64 + am * 16 + grp;
#pragma unroll
        for (int an = 0; an < 4; an++) {
            const int c0 = bn0 + wn * 32 + an * 8 + tg * 2;
            float bv0 = 0.0f, bv1 = 0.0f;
            if (bias) { bv0 = bias[c0]; bv1 = bias[c0 + 1]; }
            *(float2*)&C[(size_t)r0 * N + c0] =
                make_float2(d[am][an][0] + bv0, d[am][an][1] + bv1);
            *(float2*)&C[(size_t)(r0 + 8) * N + c0] =
                make_float2(d[am][an][2] + bv0, d[am][an][3] + bv1);
        }
    }
}

// ---------------------------------------------------------------------------
// Prep K: fp32 -> fp16 hi/lo limbs, layout [limb][h][k][d]. (proven)
// ---------------------------------------------------------------------------
__global__ __launch_bounds__(256) void prep_k(
    const float* __restrict__ qkv, __half* __restrict__ k16)
{
    const int u  = blockIdx.x * 256 + threadIdx.x;   // 0..196607
    const int hk = u >> 2, ch = u & 3;
    const int h = hk >> 12, k = hk & 4095;
    const float* src = qkv + (size_t)k * QKV_LD + EMB + h * HD + ch * 16;
    __half* dh = k16 + ((size_t)h * SEQ + k) * HD + ch * 16;

    uint32_t hi[8], lo[8];
#pragma unroll
    for (int j = 0; j < 4; j++) {
        float4 v = *(const float4*)(src + j * 4);
        split_h2(v.x, v.y, hi[j * 2], lo[j * 2]);
        split_h2(v.z, v.w, hi[j * 2 + 1], lo[j * 2 + 1]);
    }
    *(uint4*)dh       = make_uint4(hi[0], hi[1], hi[2], hi[3]);
    *(uint4*)(dh + 8) = make_uint4(hi[4], hi[5], hi[6], hi[7]);
    __half* dl = dh + LIMB;
    *(uint4*)dl       = make_uint4(lo[0], lo[1], lo[2], lo[3]);
    *(uint4*)(dl + 8) = make_uint4(lo[4], lo[5], lo[6], lo[7]);
}

// ---------------------------------------------------------------------------
// Prep V: split + transpose to [limb][h][c][k]. (proven)
// ---------------------------------------------------------------------------
__global__ __launch_bounds__(256) void prep_v(
    const float* __restrict__ qkv, __half* __restrict__ v16)
{
    __shared__ __align__(16) __half sv[2][64][80];
    const int h  = blockIdx.y, kb = blockIdx.x;
    const int t  = threadIdx.x;
    {
        const int k = t >> 2, ch = t & 3;
        const float* src = qkv + (size_t)(kb * 64 + k) * QKV_LD + 2 * EMB + h * HD + ch * 16;
#pragma unroll
        for (int j = 0; j < 16; j += 2) {
            float2 v = *(const float2*)(src + j);
            __half2 a = __floats2half2_rn(v.x, v.y);
            float2 f = __half22float2(a);
            __half2 r = __floats2half2_rn(v.x - f.x, v.y - f.y);
            const int c = ch * 16 + j;
            sv[0][c][k]     = __low2half(a);
            sv[0][c + 1][k] = __high2half(a);
            sv[1][c][k]     = __low2half(r);
            sv[1][c + 1][k] = __high2half(r);
        }
    }
    __syncthreads();
    {
        const int c = t >> 2, kc = t & 3;
        __half* dst = v16 + ((size_t)h * HD + c) * SEQ + kb * 64 + kc * 16;
#pragma unroll
        for (int j = 0; j < 2; j++) {
            *(uint4*)(dst + j * 8)        = *(const uint4*)&sv[0][c][kc * 16 + j * 8];
            *(uint4*)(dst + LIMB + j * 8) = *(const uint4*)&sv[1][c][kc * 16 + j * 8];
        }
    }
}

// ---------------------------------------------------------------------------
// HMMA flash attention, SPLIT-K over 3 key ranges. Round-10 proven inner loop
// (256 threads, 128-q tile, stride-72 smem, lagged-PV). Each split writes
// unnormalized O + per-row (m,l); merge kernel combines.
// ---------------------------------------------------------------------------
#define SQH 0                    // Q hi  [128][72]
#define SQL (SQH + 128 * 72)     // Q lo
#define SKH (SQL + 128 * 72)     // K hi  [64 key][72 d]
#define SKL (SKH + 64 * 72)      // K lo
#define SVH (SKL + 64 * 72)      // V^T hi [64 c][72 k]
#define SVL (SVH + 64 * 72)      // V^T lo
#define SPH (SVL + 64 * 72)      // P hi  [128 q][72 k]
#define SPL (SPH + 128 * 72)     // P lo
#define ATTN_HALVES (SPL + 128 * 72)          // 55296
#define ATTN_SMEM_BYTES (ATTN_HALVES * 2)     // 110592

__global__ __launch_bounds__(256, 2) void attn_hmma(
    const float* __restrict__ qkv,
    const __half* __restrict__ k16, const __half* __restrict__ v16,
    float* __restrict__ opart, float* __restrict__ ml)
{
    extern __shared__ __align__(16) __half sh[];
    const int tid  = threadIdx.x;
    const int lane = tid & 31;
    const int wid  = tid >> 5;
    const int grp  = lane >> 2;
    const int tg   = lane & 3;
    const int h    = blockIdx.y;
    const int q0   = blockIdx.x * 128;
    const int sp   = blockIdx.z;

    // Tile ranges per split: {0..21}, {22..42}, {43..63}
    const int kt0 = (sp == 0) ? 0 : (sp == 1 ? 22 : 43);
    const int kt1 = (sp == 0) ? 22 : (sp == 1 ? 43 : 64);

    // ---- Load Q tile, scale by 8*log2e, split into fp16 limbs ----
#pragma unroll
    for (int f = tid; f < 512; f += 256) {
        const int row = f >> 2, ch = f & 3;
        const float* p = qkv + (size_t)(q0 + row) * QKV_LD + h * HD + ch * 16;
        uint32_t hi[8], lo[8];
#pragma unroll
        for (int j = 0; j < 4; j++) {
            float4 v = *(const float4*)(p + j * 4);
            const float sc = 8.0f * LOG2E;
            split_h2(v.x * sc, v.y * sc, hi[j * 2], lo[j * 2]);
            split_h2(v.z * sc, v.w * sc, hi[j * 2 + 1], lo[j * 2 + 1]);
        }
        const int o = row * 72 + ch * 16;
        *(uint4*)&sh[SQH + o]     = make_uint4(hi[0], hi[1], hi[2], hi[3]);
        *(uint4*)&sh[SQH + o + 8] = make_uint4(hi[4], hi[5], hi[6], hi[7]);
        *(uint4*)&sh[SQL + o]     = make_uint4(lo[0], lo[1], lo[2], lo[3]);
        *(uint4*)&sh[SQL + o + 8] = make_uint4(lo[4], lo[5], lo[6], lo[7]);
    }

    const __half* kP = k16 + (size_t)h * SEQ * HD;
    const __half* vP = v16 + (size_t)h * HD * SEQ;

    // Chunk decode: g = tid + i*256 -> (limb, row, 8-half segment); 4 chunks.
    int clt[4], crow[4], cseg[4];
#pragma unroll
    for (int i = 0; i < 4; i++) {
        const int g = tid + i * 256;
        clt[i]  = g >> 9;
        crow[i] = (g >> 3) & 63;
        cseg[i] = g & 7;
    }

    auto sts_chunk = [&](int base_h, int base_l, int i, uint4 v) {
        const int off = (base_h + (clt[i] ? (base_l - base_h) : 0))
                        + crow[i] * 72 + cseg[i] * 8;
        *(uint2*)&sh[off]     = make_uint2(v.x, v.y);
        *(uint2*)&sh[off + 4] = make_uint2(v.z, v.w);
    };

    // ---- Preload K(kt0) ----
    {
        uint4 kc4[4];
#pragma unroll
        for (int i = 0; i < 4; i++)
            kc4[i] = *(const uint4*)(kP + clt[i] * LIMB
                         + (size_t)(kt0 * 64 + crow[i]) * HD + cseg[i] * 8);
#pragma unroll
        for (int i = 0; i < 4; i++) sts_chunk(SKH, SKL, i, kc4[i]);
    }
    __syncthreads();

    float m0 = -1e30f, m1 = -1e30f, l0 = 0.0f, l1 = 0.0f;
    float O[8][4];
#pragma unroll
    for (int nt = 0; nt < 8; nt++)
#pragma unroll
        for (int r = 0; r < 4; r++) O[nt][r] = 0.0f;

    const int qrow = (wid * 16 + grp) * 72 + tg * 2;   // Q-row / P-row base

    for (int it = kt0; it < kt1; it++) {
        const int kt = it * 64;
        const bool pfK = (it + 1) < kt1;

        // Prefetch K(it+1) and V(it) limb chunks (hidden under S-MMA + PV)
        uint4 kc4[4], vc4[4];
        if (pfK) {
#pragma unroll
            for (int i = 0; i < 4; i++)
                kc4[i] = *(const uint4*)(kP + clt[i] * LIMB
                             + (size_t)(kt + 64 + crow[i]) * HD + cseg[i] * 8);
        }
#pragma unroll
        for (int i = 0; i < 4; i++)
            vc4[i] = *(const uint4*)(vP + clt[i] * LIMB
                         + (size_t)crow[i] * SEQ + kt + cseg[i] * 8);

        // ---- S = Q K^T on tile it (3 fp16 limb products) ----
        float s[8][4];
#pragma unroll
        for (int nt = 0; nt < 8; nt++)
#pragma unroll
            for (int r = 0; r < 4; r++) s[nt][r] = 0.0f;

#pragma unroll
        for (int ks = 0; ks < 4; ks++) {
            const int qa = qrow + ks * 16;
            uint32_t ah[4], al_[4];
            ah[0] = *(const uint32_t*)&sh[SQH + qa];
            ah[1] = *(const uint32_t*)&sh[SQH + qa + 8 * 72];
            ah[2] = *(const uint32_t*)&sh[SQH + qa + 8];
            ah[3] = *(const uint32_t*)&sh[SQH + qa + 8 * 72 + 8];
            al_[0] = *(const uint32_t*)&sh[SQL + qa];
            al_[1] = *(const uint32_t*)&sh[SQL + qa + 8 * 72];
            al_[2] = *(const uint32_t*)&sh[SQL + qa + 8];
            al_[3] = *(const uint32_t*)&sh[SQL + qa + 8 * 72 + 8];
#pragma unroll
            for (int nt = 0; nt < 8; nt++) {
                const int ka = (nt * 8 + grp) * 72 + ks * 16 + tg * 2;
                uint32_t kh[2], kl[2];
                kh[0] = *(const uint32_t*)&sh[SKH + ka];
                kh[1] = *(const uint32_t*)&sh[SKH + ka + 8];
                kl[0] = *(const uint32_t*)&sh[SKL + ka];
                kl[1] = *(const uint32_t*)&sh[SKL + ka + 8];
                mma_f16(s[nt], ah, kh);
                mma_f16(s[nt], al_, kh);
                mma_f16(s[nt], ah, kl);
            }
        }

        // ---- rowmax + alpha (log2 domain) ----
        float mx0 = -1e30f, mx1 = -1e30f;
#pragma unroll
        for (int nt = 0; nt < 8; nt++) {
            mx0 = fmaxf(mx0, fmaxf(s[nt][0], s[nt][1]));
            mx1 = fmaxf(mx1, fmaxf(s[nt][2], s[nt][3]));
        }
        mx0 = fmaxf(mx0, __shfl_xor_sync(0xffffffffu, mx0, 1));
        mx0 = fmaxf(mx0, __shfl_xor_sync(0xffffffffu, mx0, 2));
        mx1 = fmaxf(mx1, __shfl_xor_sync(0xffffffffu, mx1, 1));
        mx1 = fmaxf(mx1, __shfl_xor_sync(0xffffffffu, mx1, 2));

        const float mn0 = fmaxf(m0, mx0), mn1 = fmaxf(m1, mx1);
        const float al0 = ex2f(m0 - mn0), al1 = ex2f(m1 - mn1);
        m0 = mn0; m1 = mn1;

        float sum0 = 0.0f, sum1 = 0.0f;

        if (it > kt0) {
            // ---- interleaved: PV(it-1) MMAs ‖ ex2(it) ----
#pragma unroll
            for (int kc = 0; kc < 4; kc++) {
                const int pa = qrow + kc * 16;
                uint32_t ph[4], pl[4];
                ph[0] = *(const uint32_t*)&sh[SPH + pa];
                ph[1] = *(const uint32_t*)&sh[SPH + pa + 8 * 72];
                ph[2] = *(const uint32_t*)&sh[SPH + pa + 8];
                ph[3] = *(const uint32_t*)&sh[SPH + pa + 8 * 72 + 8];
                pl[0] = *(const uint32_t*)&sh[SPL + pa];
                pl[1] = *(const uint32_t*)&sh[SPL + pa + 8 * 72];
                pl[2] = *(const uint32_t*)&sh[SPL + pa + 8];
                pl[3] = *(const uint32_t*)&sh[SPL + pa + 8 * 72 + 8];
#pragma unroll
                for (int nt = 0; nt < 8; nt++) {
                    const int va = (nt * 8 + grp) * 72 + kc * 16 + tg * 2;
                    uint32_t vh[2], vl[2];
                    vh[0] = *(const uint32_t*)&sh[SVH + va];
                    vh[1] = *(const uint32_t*)&sh[SVH + va + 8];
                    vl[0] = *(const uint32_t*)&sh[SVL + va];
                    vl[1] = *(const uint32_t*)&sh[SVL + va + 8];
                    mma_f16(O[nt], ph, vh);
                    mma_f16(O[nt], pl, vh);
                    mma_f16(O[nt], ph, vl);
                    if (nt < 2) {
                        const int e = kc * 2 + nt;
                        s[e][0] = ex2f(s[e][0] - mn0); sum0 += s[e][0];
                        s[e][1] = ex2f(s[e][1] - mn0); sum0 += s[e][1];
                        s[e][2] = ex2f(s[e][2] - mn1); sum1 += s[e][2];
                        s[e][3] = ex2f(s[e][3] - mn1); sum1 += s[e][3];
                    }
                }
            }
        } else {
#pragma unroll
            for (int nt = 0; nt < 8; nt++) {
                s[nt][0] = ex2f(s[nt][0] - mn0); sum0 += s[nt][0];
                s[nt][1] = ex2f(s[nt][1] - mn0); sum0 += s[nt][1];
                s[nt][2] = ex2f(s[nt][2] - mn1); sum1 += s[nt][2];
                s[nt][3] = ex2f(s[nt][3] - mn1); sum1 += s[nt][3];
            }
        }

        // ---- l update + O rescale (after PV(it-1) completed) ----
        sum0 += __shfl_xor_sync(0xffffffffu, sum0, 1);
        sum0 += __shfl_xor_sync(0xffffffffu, sum0, 2);
        sum1 += __shfl_xor_sync(0xffffffffu, sum1, 1);
        sum1 += __shfl_xor_sync(0xffffffffu, sum1, 2);
        l0 = l0 * al0 + sum0;
        l1 = l1 * al1 + sum1;

#pragma unroll
        for (int nt = 0; nt < 8; nt++) {
            O[nt][0] *= al0; O[nt][1] *= al0;
            O[nt][2] *= al1; O[nt][3] *= al1;
        }

        __syncwarp(0xffffffffu);   // PV reads of P(it-1) done before overwrite

        // ---- P(it) -> SMEM fp16 limbs (warp-private rows) ----
#pragma unroll
        for (int nt = 0; nt < 8; nt++) {
            uint32_t hh, ll;
            const int pa0 = qrow + nt * 8;
            split_h2(s[nt][0], s[nt][1], hh, ll);
            *(uint32_t*)&sh[SPH + pa0] = hh;
            *(uint32_t*)&sh[SPL + pa0] = ll;
            split_h2(s[nt][2], s[nt][3], hh, ll);
            *(uint32_t*)&sh[SPH + pa0 + 8 * 72] = hh;
            *(uint32_t*)&sh[SPL + pa0 + 8 * 72] = ll;
        }

        __syncthreads();   // all K(it)/V(it-1) smem reads done
        if (pfK) {
#pragma unroll
            for (int i = 0; i < 4; i++) sts_chunk(SKH, SKL, i, kc4[i]);
        }
#pragma unroll
        for (int i = 0; i < 4; i++) sts_chunk(SVH, SVL, i, vc4[i]);
        __syncthreads();   // K(it+1), V(it) visible
    }

    // ---- Epilogue: PV for the last tile of this split ----
#pragma unroll
    for (int kc = 0; kc < 4; kc++) {
        const int pa = qrow + kc * 16;
        uint32_t ph[4], pl[4];
        ph[0] = *(const uint32_t*)&sh[SPH + pa];
        ph[1] = *(const uint32_t*)&sh[SPH + pa + 8 * 72];
        ph[2] = *(const uint32_t*)&sh[SPH + pa + 8];
        ph[3] = *(const uint32_t*)&sh[SPH + pa + 8 * 72 + 8];
        pl[0] = *(const uint32_t*)&sh[SPL + pa];
        pl[1] = *(const uint32_t*)&sh[SPL + pa + 8 * 72];
        pl[2] = *(const uint32_t*)&sh[SPL + pa + 8];
        pl[3] = *(const uint32_t*)&sh[SPL + pa + 8 * 72 + 8];
#pragma unroll
        for (int nt = 0; nt < 8; nt++) {
            const int va = (nt * 8 + grp) * 72 + kc * 16 + tg * 2;
            uint32_t vh[2], vl[2];
            vh[0] = *(const uint32_t*)&sh[SVH + va];
            vh[1] = *(const uint32_t*)&sh[SVH + va + 8];
            vl[0] = *(const uint32_t*)&sh[SVL + va];
            vl[1] = *(const uint32_t*)&sh[SVL + va + 8];
            mma_f16(O[nt], ph, vh);
            mma_f16(O[nt], pl, vh);
            mma_f16(O[nt], ph, vl);
        }
    }

    // ---- Write UNNORMALIZED partial O + (m,l) per row ----
    const int r0 = q0 + wid * 16 + grp;
    float* op = opart + (size_t)sp * SEQ * EMB;
#pragma unroll
    for (int nt = 0; nt < 8; nt++) {
        const int c = h * HD + nt * 8 + tg * 2;
        *(float2*)&op[(size_t)r0 * EMB + c]       = make_float2(O[nt][0], O[nt][1]);
        *(float2*)&op[(size_t)(r0 + 8) * EMB + c] = make_float2(O[nt][2], O[nt][3]);
    }
    if (tg == 0) {
        float* mlp = ml + (((size_t)sp * HEADS + h) * SEQ) * 2;
        *(float2*)&mlp[(size_t)r0 * 2]       = make_float2(m0, l0);
        *(float2*)&mlp[(size_t)(r0 + 8) * 2] = make_float2(m1, l1);
    }
}

// ---------------------------------------------------------------------------
// Merge the 3 split-K partials: ctx = sum_p w_p*O_p / sum_p w_p*l_p,
// w_p = 2^(m_p - M). One thread per float4 of output.
// ---------------------------------------------------------------------------
__global__ __launch_bounds__(256) void merge_kernel(
    const float* __restrict__ part, const float* __restrict__ ml,
    float* __restrict__ ctx)
{
    const int idx = blockIdx.x * 256 + threadIdx.x;   // 0..786431
    const int row = idx / (EMB / 4);
    const int c4  = idx % (EMB / 4);
    const int h   = (c4 * 4) >> 6;

    float m[NSPLIT_K], lv[NSPLIT_K];
#pragma unroll
    for (int p = 0; p < NSPLIT_K; p++) {
        float2 v = *(const float2*)(ml + (((size_t)p * HEADS + h) * SEQ + row) * 2);
        m[p] = v.x; lv[p] = v.y;
    }
    const float M = fmaxf(m[0], fmaxf(m[1], m[2]));
    const float w0 = ex2f(m[0] - M), w1 = ex2f(m[1] - M), w2 = ex2f(m[2] - M);
    const float inv = 1.0f / (lv[0] * w0 + lv[1] * w1 + lv[2] * w2);

    const size_t off = (size_t)row * EMB + c4 * 4;
    float4 a = *(const float4*)(part + off);
    float4 b = *(const float4*)(part + (size_t)SEQ * EMB + off);
    float4 c = *(const float4*)(part + 2 * (size_t)SEQ * EMB + off);
    float4 o;
    o.x = (a.x * w0 + b.x * w1 + c.x * w2) * inv;
    o.y = (a.y * w0 + b.y * w1 + c.y * w2) * inv;
    o.z = (a.z * w0 + b.z * w1 + c.z * w2) * inv;
    o.w = (a.w * w0 + b.w * w1 + c.w * w2) * inv;
    *(float4*)(ctx + off) = o;
}

// ---------------------------------------------------------------------------
extern "C" void kernel_launch(void* const* d_in, const int* in_sizes, int n_in,
                              void* d_out, int out_size)
{
    (void)in_sizes; (void)n_in; (void)out_size;
    const float* x     = (const float*)d_in[0];   // [1,4096,768]
    const float* qkv_w = (const float*)d_in[1];   // [2304,768]
    const float* out_w = (const float*)d_in[2];   // [768,768]
    const float* out_b = (const float*)d_in[3];   // [768]
    float* out = (float*)d_out;                   // [1,4096,768]

    float *qkv = nullptr, *ctx = nullptr, *part = nullptr, *ml = nullptr;
    __half *k16 = nullptr, *v16 = nullptr;
    cudaGetSymbolAddress((void**)&qkv, g_qkv);
    cudaGetSymbolAddress((void**)&ctx, g_ctx);
    cudaGetSymbolAddress((void**)&k16, g_k16);
    cudaGetSymbolAddress((void**)&v16, g_v16);
    cudaGetSymbolAddress((void**)&part, g_part);
    cudaGetSymbolAddress((void**)&ml, g_ml);

    // 1) QKV projection (HMMA bf16x3)
    const int smem3 = 6 * LT * (int)sizeof(__nv_bfloat16);
    cudaFuncSetAttribute(hmma_gemm_abt<3>,
                         cudaFuncAttributeMaxDynamicSharedMemorySize, smem3);
    hmma_gemm_abt<3><<<dim3(QKV_LD / 128, SEQ / 128), 256, smem3>>>(
        x, qkv_w, nullptr, qkv, SEQ, QKV_LD, EMB);

    // 2) K/V fp16 limb pre-split
    prep_k<<<768, 256>>>(qkv, k16);
    prep_v<<<dim3(64, HEADS), 256>>>(qkv, v16);

    // 3) HMMA flash attention, split-K x3 (32 qtiles x 12 heads x 3 splits)
    cudaFuncSetAttribute(attn_hmma,
                         cudaFuncAttributeMaxDynamicSharedMemorySize, ATTN_SMEM_BYTES);
    attn_hmma<<<dim3(SEQ / 128, HEADS, NSPLIT_K), 256, ATTN_SMEM_BYTES>>>(
        qkv, k16, v16, part, ml);

    // 4) Merge partials
    merge_kernel<<<(SEQ * EMB / 4) / 256, 256>>>(part, ml, ctx);

    // 5) Output projection + bias (HMMA bf16x2)
    const int smem2 = 4 * LT * (int)sizeof(__nv_bfloat16);
    cudaFuncSetAttribute(hmma_gemm_abt<2>,
                         cudaFuncAttributeMaxDynamicSharedMemorySize, smem2);
    hmma_gemm_abt<2><<<dim3(EMB / 128, SEQ / 128), 256, smem2>>>(
        ctx, out_w, out_b, out, SEQ, EMB, EMB);
}